// round 17
// baseline (speedup 1.0000x reference)
#include <cuda_runtime.h>
#include <math.h>

// ---------------- problem constants ----------------
constexpr int   B_TOT  = 1000000;
constexpr int   SPIN   = 1000;
constexpr int   TRAIN  = 800000;
constexpr float ML     = 2.9086f;
constexpr float SL     = 1.898f;
constexpr float U1MAX  = 221.519f;

// geometry
constexpr int CHUNK   = 32;                   // steps per chunk
constexpr int WARMCH  = 2;                    // warm-up chunks (64 steps)
constexpr int NCH     = B_TOT / CHUNK;        // 31250
constexpr int CPB     = 32;                   // chunks per block (warp 0 scans)
constexpr int TPB     = CPB * CHUNK;          // 1024 timesteps per block
constexpr int BLK     = 256;
constexpr int GRID_B  = (B_TOT + TPB - 1) / TPB;   // 977
constexpr int ROWS    = CPB + WARMCH;              // 34 window rows

constexpr int RBLOCKS = 132;
__device__ double g_part[RBLOCKS][2];
__device__ int    g_rcnt = 0;                 // reduce-done counter (self-resetting)
__device__ float  g_obsstd;

// ---------------- math helpers ----------------
__device__ __forceinline__ float tanha(float z) {
    float r;
    asm("tanh.approx.f32 %0, %1;" : "=f"(r) : "f"(z));
    return r;
}

__device__ __forceinline__ void stcs4(float* p, float4 v) {
    asm volatile("st.global.cs.v4.f32 [%0], {%1, %2, %3, %4};"
                 :: "l"(p), "f"(v.x), "f"(v.y), "f"(v.z), "f"(v.w) : "memory");
}

struct P {
    float koo, coo;        // zo = koo*c + coo
    float kib, cib, kibu;  // zi = kib*c + (kibu*u1 + cib)
    float kol, col;        // zl = kol*u2 + col
    float hoo1, hol1;      // 0.5*oo1, 0.5*ol1
};

__device__ __forceinline__ P load_params(
    const float* cmean, const float* cstd,
    const float* wro, const float* wrl, const float* wrf,
    const float* b0o, const float* wb1o,
    const float* b0l, const float* wb2l,
    const float* wb1u, const float* b0u)
{
    P p;
    float mo = cmean[0];
    float inv_so = 1.0f / cstd[0];
    float eo = __expf(wro[0]);
    float el = __expf(wrl[0]);
    float ef = __expf(wrf[0]);
    float id = __fdividef(1.0f, eo + el + ef);
    p.hoo1 = 0.5f * eo * id;
    p.hol1 = 0.5f * el * id;
    float w1o = wb1o[0], w1u = wb1u[0], w2l = wb2l[0];
    p.koo  = 0.5f * w1o * inv_so;
    p.coo  = 0.5f * (b0o[0] - mo * inv_so * w1o);
    p.kib  = 0.5f * w1u * inv_so;
    p.cib  = 0.5f * (b0u[0] - mo * inv_so * w1u);
    p.kibu = 0.5f * w1u / U1MAX;
    p.kol  = 0.5f * w2l / SL;
    p.col  = 0.5f * (b0l[0] - (ML / SL) * w2l);
    return p;
}

// one recurrence step (state only). chain: fma -> tanh -> fma -> fma.
__device__ __forceinline__ float step_c(float c, float u1, float u2, const P& p) {
    float hu1 = 0.5f * u1;
    float zib = fmaf(u1, p.kibu, p.cib);
    float zl  = fmaf(u2, p.kol, p.col);
    float ol  = fmaf(tanha(zl), p.hol1, p.hol1);
    float zo  = fmaf(c, p.koo, p.coo);
    float zi  = fmaf(c, p.kib, zib);
    float to  = tanha(zo);
    float ti  = tanha(zi);
    float hc  = p.hoo1 * c;
    float olc_c = ol * c;
    float L   = (c > 0.0f) ? fminf(olc_c, u2) : olc_c;
    float base = ((c - hc) + hu1) - L;
    return fmaf(-hu1, ti, fmaf(-hc, to, base));
}

// ---------------- kernel A: reduction partials + obsstd fold --------------
__global__ __launch_bounds__(256) void reduce_k(const float* __restrict__ y) {
    __shared__ double shred[2][8];
    __shared__ int s_last;
    const int tid = threadIdx.x;
    const float4* y4 = reinterpret_cast<const float4*>(y + SPIN);
    const int n4 = (TRAIN - SPIN) / 4;
    double s = 0.0, s2 = 0.0;
    for (int i = blockIdx.x * 256 + tid; i < n4; i += RBLOCKS * 256) {
        float4 v = __ldg(y4 + i);
        double a = v.x, b = v.y, cc = v.z, d = v.w;
        s  += (a + b) + (cc + d);
        s2 += (a * a + b * b) + (cc * cc + d * d);
    }
    #pragma unroll
    for (int o = 16; o > 0; o >>= 1) {
        s  += __shfl_down_sync(0xffffffffu, s,  o);
        s2 += __shfl_down_sync(0xffffffffu, s2, o);
    }
    int lane = tid & 31, warp = tid >> 5;
    if (lane == 0) { shred[0][warp] = s; shred[1][warp] = s2; }
    __syncthreads();
    if (tid == 0) {
        s = 0.0; s2 = 0.0;
        #pragma unroll
        for (int w = 0; w < 8; ++w) { s += shred[0][w]; s2 += shred[1][w]; }
        g_part[blockIdx.x][0] = s;
        g_part[blockIdx.x][1] = s2;
        __threadfence();
        s_last = (atomicAdd(&g_rcnt, 1) == RBLOCKS - 1) ? 1 : 0;
    }
    __syncthreads();
    if (s_last && tid < 32) {
        __threadfence();
        double a = 0.0, a2 = 0.0;
        for (int i = tid; i < RBLOCKS; i += 32) {
            a  += g_part[i][0];
            a2 += g_part[i][1];
        }
        #pragma unroll
        for (int o = 16; o > 0; o >>= 1) {
            a  += __shfl_down_sync(0xffffffffu, a,  o);
            a2 += __shfl_down_sync(0xffffffffu, a2, o);
        }
        if (tid == 0) {
            double n = (double)(TRAIN - SPIN);
            g_obsstd = (float)sqrt((a2 - a * a / n) / (n - 1.0));
            g_rcnt = 0;                               // reset for next replay
        }
    }
    cudaTriggerProgrammaticLaunchCompletion();
}

// ---------------- kernel B: self-sufficient scan + sweep -------------------
// Each block: stage 34-chunk x window -> warp 0 scans its 32 chunks (c into
// SMEM) -> grid-dep sync (obsstd) -> 256 threads sweep 4 timesteps each,
// writing all 13 output streams. No inter-block dependencies.
__global__ __launch_bounds__(BLK) void fused_k(
    const float4* __restrict__ x4,
    float* __restrict__ out,
    const int* __restrict__ time_lag_p,
    const float* cmean, const float* cstd,
    const float* wro, const float* wrl, const float* wrf,
    const float* b0o, const float* wb1o,
    const float* b0l, const float* wb2l,
    const float* wb1u, const float* b0u)
{
    __shared__ float2 sx[ROWS][CHUNK + 1];            // 34 x 33 float2 = 9.0KB
    __shared__ float  sc[CPB][CHUNK + 1];             // 32 x 33 float  = 4.2KB

    const int tid = threadIdx.x;
    const int bid = blockIdx.x;
    const int b0  = bid * CPB;                        // first chunk of block
    const int base_t = (b0 - WARMCH) * CHUNK;         // window start (may be <0)

    const P p = load_params(cmean, cstd, wro, wrl, wrf, b0o, wb1o, b0l, wb2l, wb1u, b0u);
    const int tl = __ldg(time_lag_p);

    // ---- stage window: ROWS*CHUNK timesteps, 2 per float4 ----
    constexpr int NLD4 = ROWS * CHUNK / 2;            // 544
    #pragma unroll
    for (int i = tid; i < NLD4; i += BLK) {
        int t = base_t + 2 * i;
        float4 v = make_float4(0.f, 0.f, 0.f, 0.f);
        if (t >= 0 && t < B_TOT) v = __ldg(x4 + (t >> 1));
        int li = 2 * i;
        int row = li >> 5, s = li & 31;
        sx[row][s]     = make_float2(v.x, v.y);
        sx[row][s + 1] = make_float2(v.z, v.w);
    }
    __syncthreads();

    // ---- warp 0 scans the block's 32 chunks ----
    if (tid < 32) {
        const int chunk = b0 + tid;
        if (chunk < NCH) {
            float c = 0.0f;
            #pragma unroll
            for (int d = WARMCH; d >= 1; --d) {
                if (chunk - d >= 0) {
                    const int row = tid + WARMCH - d;
                    #pragma unroll 8
                    for (int s = 0; s < CHUNK; ++s) {
                        float2 u = sx[row][s];
                        c = step_c(c, u.x, u.y, p);
                    }
                }
            }
            const int row = tid + WARMCH;
            #pragma unroll 8
            for (int s = 0; s < CHUNK; ++s) {
                float2 u = sx[row][s];
                sc[tid][s] = c;                       // pre-update state
                c = step_c(c, u.x, u.y, p);
            }
        }
    }

    // obsstd only needed below — reduce kernel is long done by now
    cudaGridDependencySynchronize();
    __syncthreads();

    // ---- sweep: 4 consecutive timesteps per thread ----
    const int i0 = tid * 4;                           // 0..1020
    const int t  = bid * TPB + i0;
    if (t >= B_TOT) return;
    const int r  = i0 >> 5;                           // chunk row
    const int s0 = i0 & 31;

    const float os = g_obsstd;
    const size_t B = (size_t)B_TOT;

    float cv[4], u1v[4], u2v[4];
    #pragma unroll
    for (int k = 0; k < 4; ++k) {
        cv[k] = sc[r][s0 + k];
        float2 u = sx[r + WARMCH][s0 + k];
        u1v[k] = u.x;
        u2v[k] = u.y;
    }

    float oo[4], ib[4], ol[4], olc[4], olcc[4], m[4];
    #pragma unroll
    for (int j = 0; j < 4; ++j) {
        float c = cv[j], u1 = u1v[j], u2 = u2v[j];
        float zo = fmaf(c, p.koo, p.coo);
        float zi = fmaf(c, p.kib, fmaf(u1, p.kibu, p.cib));
        float zl = fmaf(u2, p.kol, p.col);
        oo[j] = fmaf(tanha(zo), p.hoo1, p.hoo1);
        ib[j] = fmaf(tanha(zi), 0.5f, 0.5f);
        ol[j] = fmaf(tanha(zl), p.hol1, p.hol1);
        bool cp = (c > 0.0f);
        olc[j]  = cp ? fminf(ol[j], __fdividef(u2, c)) : ol[j];
        olcc[j] = cp ? fminf(ol[j] * c, u2) : ol[j] * c;
        m[j] = (t + j >= tl) ? 1.0f : 0.0f;
    }

    float4 v;
    float h0 = m[0] * fmaf(oo[0], cv[0], ib[0] * u1v[0]);
    float h1 = m[1] * fmaf(oo[1], cv[1], ib[1] * u1v[1]);
    float h2 = m[2] * fmaf(oo[2], cv[2], ib[2] * u1v[2]);
    float h3 = m[3] * fmaf(oo[3], cv[3], ib[3] * u1v[3]);
    stcs4(out + t, make_float4(h0, h1, h2, h3));                      // h_n
    v = make_float4(m[0] * cv[0], m[1] * cv[1], m[2] * cv[2], m[3] * cv[3]);
    stcs4(out + B + t, v);                                            // c_n
    v = make_float4(m[0] * ol[0] * cv[0], m[1] * ol[1] * cv[1],
                    m[2] * ol[2] * cv[2], m[3] * ol[3] * cv[3]);
    stcs4(out + 2 * B + t, v);                                        // l_n
    v = make_float4(m[0] * olcc[0], m[1] * olcc[1], m[2] * olcc[2], m[3] * olcc[3]);
    stcs4(out + 3 * B + t, v);                                        // lc_n
    v = make_float4(m[0] * ib[0] * u1v[0], m[1] * ib[1] * u1v[1],
                    m[2] * ib[2] * u1v[2], m[3] * ib[3] * u1v[3]);
    stcs4(out + 4 * B + t, v);                                        // bp_n
    v = make_float4(m[0] * ib[0], m[1] * ib[1], m[2] * ib[2], m[3] * ib[3]);
    stcs4(out + 5 * B + t, v);                                        // g_ib
    v = make_float4(m[0] * oo[0], m[1] * oo[1], m[2] * oo[2], m[3] * oo[3]);
    stcs4(out + 6 * B + t, v);                                        // g_oo
    v = make_float4(m[0] * ol[0], m[1] * ol[1], m[2] * ol[2], m[3] * ol[3]);
    stcs4(out + 7 * B + t, v);                                        // g_ol
    v = make_float4(m[0] * olc[0], m[1] * olc[1], m[2] * olc[2], m[3] * olc[3]);
    stcs4(out + 8 * B + t, v);                                        // g_olc
    v = make_float4(m[0] * (1.0f - oo[0] - olc[0]), m[1] * (1.0f - oo[1] - olc[1]),
                    m[2] * (1.0f - oo[2] - olc[2]), m[3] * (1.0f - oo[3] - olc[3]));
    stcs4(out + 9 * B + t, v);                                        // g_f
    stcs4(out + 10 * B + 2 * (size_t)t,
          make_float4(h0, m[0] * os, h1, m[1] * os));                 // h_nout lo
    stcs4(out + 10 * B + 2 * (size_t)t + 4,
          make_float4(h2, m[2] * os, h3, m[3] * os));                 // h_nout hi
    v = make_float4(m[0] * os, m[1] * os, m[2] * os, m[3] * os);
    stcs4(out + 12 * B + t, v);                                       // obs_std
}

// ---------------- launch ----------------
extern "C" void kernel_launch(void* const* d_in, const int* in_sizes, int n_in,
                              void* d_out, int out_size) {
    const float4* x4    = (const float4*)d_in[0];
    const int*    tl    = (const int*)   d_in[2];
    const float*  y_obs = (const float*) d_in[3];
    const float*  cmean = (const float*) d_in[4];
    const float*  cstd  = (const float*) d_in[5];
    const float*  wro   = (const float*) d_in[6];
    const float*  wrl   = (const float*) d_in[7];
    const float*  wrf   = (const float*) d_in[8];
    const float*  b0o   = (const float*) d_in[9];
    const float*  wb1o  = (const float*) d_in[10];
    const float*  b0l   = (const float*) d_in[11];
    const float*  wb2l  = (const float*) d_in[12];
    const float*  wb1u  = (const float*) d_in[13];
    const float*  b0u   = (const float*) d_in[14];
    float* out = (float*)d_out;

    reduce_k<<<RBLOCKS, 256>>>(y_obs);

    // dependent launch with PDL: staging + scan overlap the reduce kernel
    cudaLaunchConfig_t cfg = {};
    cfg.gridDim  = dim3(GRID_B);
    cfg.blockDim = dim3(BLK);
    cfg.stream   = 0;
    cudaLaunchAttribute attrs[1];
    attrs[0].id = cudaLaunchAttributeProgrammaticStreamSerialization;
    attrs[0].val.programmaticStreamSerializationAllowed = 1;
    cfg.attrs    = attrs;
    cfg.numAttrs = 1;
    cudaLaunchKernelEx(&cfg, fused_k, x4, (float*)out, tl,
        cmean, cstd, wro, wrl, wrf, b0o, wb1o, b0l, wb2l, wb1u, b0u);
}